// round 9
// baseline (speedup 1.0000x reference)
#include <cuda_runtime.h>

typedef unsigned long long u64;
typedef unsigned int u32;

#define VOCAB   65
#define SQRT_C  5.656854249492381f   // faithful bug: scores MULTIPLIED by sqrt(32)

// ---------------- scratch (device globals; no allocations allowed) ----------
__device__ __align__(16) float g_Qtab[520 * 32];
__device__ __align__(16) float g_Ktab[520 * 32];   // pre-scaled by SQRT_C
__device__ __align__(16) float g_Vtab[520 * 32];
__device__ float    g_loss;
__device__ unsigned g_done;

// ---------------- packed weights: one constant block, one memcpy ------------
#define WLM_STRIDE 68          // padded vocab row stride (16B-aligned rows)
#define OFF_WMLP   0           // [c][c2] 1024
#define OFF_BMLP   1024        // 32
#define OFF_BLM    1056        // 68 (65 + zero pad)
#define OFF_WLM    1124        // [c][v] 32*68 = 2176
#define PACK_N     3300
__device__   __align__(16) float g_pack[PACK_N];
__constant__ __align__(16) float c_all[PACK_N];

// ---------------- packed f32x2 helpers (sm_103a) ----------------------------
__device__ __forceinline__ u64 fma2(u64 a, u64 b, u64 c) {
    u64 d; asm("fma.rn.f32x2 %0, %1, %2, %3;" : "=l"(d) : "l"(a), "l"(b), "l"(c)); return d;
}
__device__ __forceinline__ u64 add2(u64 a, u64 b) {
    u64 d; asm("add.rn.f32x2 %0, %1, %2;" : "=l"(d) : "l"(a), "l"(b)); return d;
}
__device__ __forceinline__ float hadd2(u64 a) {
    float lo, hi; asm("mov.b64 {%0,%1}, %2;" : "=f"(lo), "=f"(hi) : "l"(a)); return lo + hi;
}
__device__ __forceinline__ u64 pack2(float lo, float hi) {
    u64 r; asm("mov.b64 %0, {%1,%2};" : "=l"(r) : "f"(lo), "f"(hi)); return r;
}
__device__ __forceinline__ float lo2(u64 a) {
    float lo, hi; asm("mov.b64 {%0,%1}, %2;" : "=f"(lo), "=f"(hi) : "l"(a)); return lo;
}
__device__ __forceinline__ float hi2(u64 a) {
    float lo, hi; asm("mov.b64 {%0,%1}, %2;" : "=f"(lo), "=f"(hi) : "l"(a)); return hi;
}
__device__ __forceinline__ ulonglong2 ldc4(const float* p) {
    return *reinterpret_cast<const ulonglong2*>(p);
}

// Precompute Q/K/V tables AND pack weights for the single constant upload.
__global__ void k_tables(const float* __restrict__ tok_emb,
                         const float* __restrict__ pos_emb,
                         const float* __restrict__ Wq,
                         const float* __restrict__ Wk,
                         const float* __restrict__ Wv,
                         const float* __restrict__ Wmlp,
                         const float* __restrict__ bmlp,
                         const float* __restrict__ Wlm,
                         const float* __restrict__ blm) {
    int i = blockIdx.x * blockDim.x + threadIdx.x;
    if (i == 0) { g_loss = 0.0f; g_done = 0u; }
    if (i < 520 * 32) {
        int row = i >> 5, c = i & 31;
        int t = row / 65, tok = row % 65;
        int h = c >> 3, d = c & 7;
        float aq = 0.f, ak = 0.f, av = 0.f;
#pragma unroll
        for (int cc = 0; cc < 32; cc++) {
            float xv = tok_emb[tok * 32 + cc] + pos_emb[t * 32 + cc];
            int wi = h * 256 + cc * 8 + d;
            aq = fmaf(xv, Wq[wi], aq);
            ak = fmaf(xv, Wk[wi], ak);
            av = fmaf(xv, Wv[wi], av);
        }
        g_Qtab[i] = aq;
        g_Ktab[i] = ak * SQRT_C;
        g_Vtab[i] = av;
    } else {
        int i2 = i - 520 * 32;
        if (i2 < PACK_N) {
            float v;
            if (i2 < OFF_BMLP)      v = Wmlp[i2];
            else if (i2 < OFF_BLM)  v = bmlp[i2 - OFF_BMLP];
            else if (i2 < OFF_WLM) {
                int j = i2 - OFF_BLM;
                v = (j < 65) ? blm[j] : 0.0f;
            } else {
                int j  = i2 - OFF_WLM;
                int c  = j / WLM_STRIDE;
                int vv = j - c * WLM_STRIDE;
                v = (vv < 65) ? Wlm[c * 65 + vv] : 0.0f;
            }
            g_pack[i2] = v;
        }
    }
}

#define KV_STRIDE 260       // floats per sequence: +4 banks per ls -> conflict-free
#define V_BASE    8320      // 32 * 260

// attention for ONE token; K/V already staged. Produces ov[32].
__device__ __forceinline__ void attention_one(const float* __restrict__ s_un,
                                              int ls, int t, int qrow,
                                              float* __restrict__ ov) {
#pragma unroll
    for (int hp = 0; hp < 2; hp++) {
        u64 q2[8];
        {
            const ulonglong2* q4 =
                reinterpret_cast<const ulonglong2*>(g_Qtab + qrow + hp * 16);
#pragma unroll
            for (int j = 0; j < 4; j++) {
                ulonglong2 a = q4[j];
                q2[2 * j] = a.x; q2[2 * j + 1] = a.y;
            }
        }
        float sc[2][8];
        const float* kb = s_un + ls * KV_STRIDE + hp * 16;
#pragma unroll
        for (int s = 0; s < 8; s++) {
            const ulonglong2* kr = reinterpret_cast<const ulonglong2*>(kb + s * 32);
            ulonglong2 a = kr[0], b = kr[1], c = kr[2], d = kr[3];
            u64 e0 = 0ull, e1 = 0ull, f0 = 0ull, f1 = 0ull;
            e0 = fma2(q2[0], a.x, e0); e1 = fma2(q2[1], a.y, e1);
            e0 = fma2(q2[2], b.x, e0); e1 = fma2(q2[3], b.y, e1);
            f0 = fma2(q2[4], c.x, f0); f1 = fma2(q2[5], c.y, f1);
            f0 = fma2(q2[6], d.x, f0); f1 = fma2(q2[7], d.y, f1);
            float se = hadd2(add2(e0, e1));
            float sf = hadd2(add2(f0, f1));
            sc[0][s] = (s <= t) ? se : -1e30f;
            sc[1][s] = (s <= t) ? sf : -1e30f;
        }
        float rinv[2];
#pragma unroll
        for (int hh = 0; hh < 2; hh++) {
            float m = sc[hh][0];
#pragma unroll
            for (int s = 1; s < 8; s++) m = fmaxf(m, sc[hh][s]);
            float sum = 0.f;
#pragma unroll
            for (int s = 0; s < 8; s++) {
                float e = __expf(sc[hh][s] - m);   // masked lanes underflow to 0
                sc[hh][s] = e;
                sum += e;
            }
            rinv[hh] = __fdividef(1.0f, sum);
        }
        u64 oacc[8];
#pragma unroll
        for (int j = 0; j < 8; j++) oacc[j] = 0ull;
        const float* vb = s_un + V_BASE + ls * KV_STRIDE + hp * 16;
#pragma unroll
        for (int s = 0; s < 8; s++) {
            const ulonglong2* vr = reinterpret_cast<const ulonglong2*>(vb + s * 32);
            ulonglong2 a = vr[0], b = vr[1], c = vr[2], d = vr[3];
            float p0 = sc[0][s] * rinv[0];
            float p1 = sc[1][s] * rinv[1];
            u64 p02 = pack2(p0, p0), p12 = pack2(p1, p1);
            oacc[0] = fma2(p02, a.x, oacc[0]); oacc[1] = fma2(p02, a.y, oacc[1]);
            oacc[2] = fma2(p02, b.x, oacc[2]); oacc[3] = fma2(p02, b.y, oacc[3]);
            oacc[4] = fma2(p12, c.x, oacc[4]); oacc[5] = fma2(p12, c.y, oacc[5]);
            oacc[6] = fma2(p12, d.x, oacc[6]); oacc[7] = fma2(p12, d.y, oacc[7]);
        }
#pragma unroll
        for (int j = 0; j < 8; j++) {
            ov[hp * 16 + 2 * j]     = lo2(oacc[j]);
            ov[hp * 16 + 2 * j + 1] = hi2(oacc[j]);
        }
    }
}

// Main fused kernel: TWO tokens per thread (rows b*256+tid and +128).
// Weight loads amortized across the token pair; all weights on constant port.
__global__ __launch_bounds__(128, 3)
void k_main(const int* __restrict__ idx, const int* __restrict__ tgt,
            float* __restrict__ out, int write_logits,
            int loss_idx, float inv_n, int nblocks) {
    // union: K[32*260] | V[32*260]  -->  logits stage [256][65] dense (16640 floats)
    __shared__ __align__(16) float s_un[16640];
    __shared__ float               s_lred[4];

    const float* c_wmlp = c_all + OFF_WMLP;
    const float* c_bmlp = c_all + OFF_BMLP;
    const float* c_blm  = c_all + OFF_BLM;
    const float* c_wlm  = c_all + OFF_WLM;

    const int tid   = threadIdx.x;
    const int ls0   = tid >> 3;                // sequences 0..15 (token0)
    const int ls1   = ls0 + 16;                // sequences 16..31 (token1)
    const int t     = tid & 7;
    const int rowg0 = blockIdx.x * 256 + tid;
    const int rowg1 = rowg0 + 128;
    const int tok0  = idx[rowg0];
    const int tok1  = idx[rowg1];
    const int tgt0  = tgt[rowg0];
    const int tgt1  = tgt[rowg1];
    const int qrow0 = (t * 65 + tok0) * 32;
    const int qrow1 = (t * 65 + tok1) * 32;

    // stage K,V for BOTH tokens
    {
        const float4* k0 = reinterpret_cast<const float4*>(g_Ktab + qrow0);
        const float4* v0 = reinterpret_cast<const float4*>(g_Vtab + qrow0);
        const float4* k1 = reinterpret_cast<const float4*>(g_Ktab + qrow1);
        const float4* v1 = reinterpret_cast<const float4*>(g_Vtab + qrow1);
        float4* sk0 = reinterpret_cast<float4*>(s_un + ls0 * KV_STRIDE + t * 32);
        float4* sv0 = reinterpret_cast<float4*>(s_un + V_BASE + ls0 * KV_STRIDE + t * 32);
        float4* sk1 = reinterpret_cast<float4*>(s_un + ls1 * KV_STRIDE + t * 32);
        float4* sv1 = reinterpret_cast<float4*>(s_un + V_BASE + ls1 * KV_STRIDE + t * 32);
#pragma unroll
        for (int j = 0; j < 8; j++) {
            sk0[j] = k0[j]; sv0[j] = v0[j];
            sk1[j] = k1[j]; sv1[j] = v1[j];
        }
    }
    __syncthreads();

    // ----- attention for both tokens -----
    float ov0[32], ov1[32];
    attention_one(s_un, ls0, t, qrow0, ov0);
    attention_one(s_un, ls1, t, qrow1, ov1);
    __syncthreads();   // done reading K/V -> union becomes logits stage

    // ----- joint MLP in two half-passes (c2 halves); weights loaded ONCE per pair
    float y0[32], y1[32];
#pragma unroll
    for (int half = 0; half < 2; half++) {
        const int cb = half * 16;
        u64 m0[8], m1[8];
#pragma unroll
        for (int p = 0; p < 4; p++) {
            ulonglong2 b = ldc4(c_bmlp + cb + 4 * p);
            m0[2 * p] = b.x; m0[2 * p + 1] = b.y;
            m1[2 * p] = b.x; m1[2 * p + 1] = b.y;
        }
#pragma unroll
        for (int c = 0; c < 32; c++) {
            u64 x0 = pack2(ov0[c], ov0[c]);
            u64 x1 = pack2(ov1[c], ov1[c]);
            const float* wr = c_wmlp + c * 32 + cb;
#pragma unroll
            for (int q = 0; q < 4; q++) {
                ulonglong2 w = ldc4(wr + 4 * q);
                m0[2 * q]     = fma2(x0, w.x, m0[2 * q]);
                m0[2 * q + 1] = fma2(x0, w.y, m0[2 * q + 1]);
                m1[2 * q]     = fma2(x1, w.x, m1[2 * q]);
                m1[2 * q + 1] = fma2(x1, w.y, m1[2 * q + 1]);
            }
        }
#pragma unroll
        for (int p = 0; p < 8; p++) {
            y0[cb + 2 * p]     = fmaxf(lo2(m0[p]), 0.f);
            y0[cb + 2 * p + 1] = fmaxf(hi2(m0[p]), 0.f);
            y1[cb + 2 * p]     = fmaxf(lo2(m1[p]), 0.f);
            y1[cb + 2 * p + 1] = fmaxf(hi2(m1[p]), 0.f);
        }
    }

    // ----- joint lm-head: 16 vocab per chunk, both tokens; online LSE -----
    float* sr0 = s_un + tid * 65;
    float* sr1 = s_un + (128 + tid) * 65;
    float ma = -1e30f, sa = 0.f;     // token0 LSE
    float mb = -1e30f, sb = 0.f;     // token1 LSE

#pragma unroll
    for (int chunk = 0; chunk < 4; chunk++) {
        const int vb = chunk * 16;
        u64 a0[8], a1[8];
#pragma unroll
        for (int p = 0; p < 4; p++) {
            ulonglong2 b = ldc4(c_blm + vb + 4 * p);
            a0[2 * p] = b.x; a0[2 * p + 1] = b.y;
            a1[2 * p] = b.x; a1[2 * p + 1] = b.y;
        }
#pragma unroll
        for (int c = 0; c < 32; c++) {
            u64 yb0 = pack2(y0[c], y0[c]);
            u64 yb1 = pack2(y1[c], y1[c]);
            const float* wr = c_wlm + c * WLM_STRIDE + vb;
#pragma unroll
            for (int q = 0; q < 4; q++) {
                ulonglong2 w = ldc4(wr + 4 * q);
                a0[2 * q]     = fma2(yb0, w.x, a0[2 * q]);
                a0[2 * q + 1] = fma2(yb0, w.y, a0[2 * q + 1]);
                a1[2 * q]     = fma2(yb1, w.x, a1[2 * q]);
                a1[2 * q + 1] = fma2(yb1, w.y, a1[2 * q + 1]);
            }
        }
        // store + online LSE over these 16 logits, both tokens
        float l[16], cm;
        cm = -1e30f;
#pragma unroll
        for (int p = 0; p < 8; p++) {
            l[2 * p] = lo2(a0[p]); l[2 * p + 1] = hi2(a0[p]);
            sr0[vb + 2 * p]     = l[2 * p];
            sr0[vb + 2 * p + 1] = l[2 * p + 1];
            cm = fmaxf(cm, fmaxf(l[2 * p], l[2 * p + 1]));
        }
        {
            float mn = fmaxf(ma, cm);
            float s2 = sa * __expf(ma - mn);
#pragma unroll
            for (int p = 0; p < 16; p++) s2 += __expf(l[p] - mn);
            ma = mn; sa = s2;
        }
        cm = -1e30f;
#pragma unroll
        for (int p = 0; p < 8; p++) {
            l[2 * p] = lo2(a1[p]); l[2 * p + 1] = hi2(a1[p]);
            sr1[vb + 2 * p]     = l[2 * p];
            sr1[vb + 2 * p + 1] = l[2 * p + 1];
            cm = fmaxf(cm, fmaxf(l[2 * p], l[2 * p + 1]));
        }
        {
            float mn = fmaxf(mb, cm);
            float s2 = sb * __expf(mb - mn);
#pragma unroll
            for (int p = 0; p < 16; p++) s2 += __expf(l[p] - mn);
            mb = mn; sb = s2;
        }
    }
    {   // epilogue: v = 64 for both tokens (pair partner v=65 is zero pad)
        u64 bb = *reinterpret_cast<const u64*>(c_blm + 64);
        u64 a0 = bb, a1 = bb;
#pragma unroll
        for (int c = 0; c < 32; c++) {
            u64 w = *reinterpret_cast<const u64*>(c_wlm + c * WLM_STRIDE + 64);
            a0 = fma2(pack2(y0[c], y0[c]), w, a0);
            a1 = fma2(pack2(y1[c], y1[c]), w, a1);
        }
        float l0 = lo2(a0), l1 = lo2(a1);
        sr0[64] = l0;
        sr1[64] = l1;
        float mn = fmaxf(ma, l0);
        sa = sa * __expf(ma - mn) + __expf(l0 - mn);
        ma = mn;
        mn = fmaxf(mb, l1);
        sb = sb * __expf(mb - mn) + __expf(l1 - mn);
        mb = mn;
    }
    float lossi = (ma + __logf(sa)) - sr0[tgt0]
                + (mb + __logf(sb)) - sr1[tgt1];

    // warp then block reduce, one atomic per block; last block writes mean
#pragma unroll
    for (int off = 16; off > 0; off >>= 1)
        lossi += __shfl_down_sync(0xffffffffu, lossi, off);
    if ((tid & 31) == 0) s_lred[tid >> 5] = lossi;
    __syncthreads();    // also guarantees stage[] fully written for the bulk store
    if (tid == 0) {
        atomicAdd(&g_loss, s_lred[0] + s_lred[1] + s_lred[2] + s_lred[3]);
        __threadfence();
        unsigned prev = atomicAdd(&g_done, 1u);
        if ((int)prev == nblocks - 1 && loss_idx >= 0)
            out[loss_idx] = g_loss * inv_n;
    }

    // ----- single TMA bulk store: SMEM stage -> GMEM logits (66560 B) -----
    if (write_logits && tid == 0) {
        u32 saddr;
        asm("{ .reg .u64 tmp; cvta.to.shared.u64 tmp, %1; cvt.u32.u64 %0, tmp; }"
            : "=r"(saddr) : "l"(s_un));
        const float* gdst = out + (size_t)blockIdx.x * 16640;
        asm volatile("fence.proxy.async.shared::cta;" ::: "memory");
        asm volatile("cp.async.bulk.global.shared::cta.bulk_group [%0], [%1], %2;"
                     :: "l"(gdst), "r"(saddr), "r"(66560) : "memory");
        asm volatile("cp.async.bulk.commit_group;" ::: "memory");
        asm volatile("cp.async.bulk.wait_group.read 0;" ::: "memory");
    }
}

extern "C" void kernel_launch(void* const* d_in, const int* in_sizes, int n_in,
                              void* d_out, int out_size) {
    const int*   idx     = (const int*)d_in[0];
    const int*   targets = (const int*)d_in[1];
    const float* tok_emb = (const float*)d_in[2];
    const float* pos_emb = (const float*)d_in[3];
    const float* Wq      = (const float*)d_in[4];
    const float* Wk      = (const float*)d_in[5];
    const float* Wv      = (const float*)d_in[6];
    const float* Wmlp    = (const float*)d_in[7];
    const float* bmlp    = (const float*)d_in[8];
    const float* Wlm     = (const float*)d_in[9];
    const float* blm     = (const float*)d_in[10];
    float* out = (float*)d_out;

    const long nrows = in_sizes[0];           // B*T = 524288
    const long total = nrows * VOCAB;
    int write_logits = ((long)out_size >= total) ? 1 : 0;
    int loss_idx = -1;
    if ((long)out_size == total + 1) loss_idx = (int)total;
    else if (out_size == 1)          { loss_idx = 0; write_logits = 0; }

    int work = 520 * 32 + PACK_N;
    k_tables<<<(work + 255) / 256, 256>>>(tok_emb, pos_emb, Wq, Wk, Wv,
                                          Wmlp, bmlp, Wlm, blm);
    {
        void* src = nullptr;
        cudaGetSymbolAddress(&src, g_pack);
        cudaMemcpyToSymbolAsync(c_all, src, PACK_N * sizeof(float), 0,
                                cudaMemcpyDeviceToDevice);
    }

    int nblocks = (int)(nrows / 256);
    k_main<<<nblocks, 128>>>(idx, targets, out, write_logits, loss_idx,
                             1.0f / (float)nrows, nblocks);
}

// round 10
// speedup vs baseline: 1.2617x; 1.2617x over previous
#include <cuda_runtime.h>

typedef unsigned long long u64;
typedef unsigned int u32;

#define VOCAB   65
#define SQRT_C  5.656854249492381f   // faithful bug: scores MULTIPLIED by sqrt(32)

// ---------------- scratch (device globals; no allocations allowed) ----------
__device__ __align__(16) float g_Qtab[520 * 32];
__device__ __align__(16) float g_Ktab[520 * 32];   // pre-scaled by SQRT_C
__device__ __align__(16) float g_Vtab[520 * 32];
__device__ float    g_loss;
__device__ unsigned g_done;

// ---------------- packed weights: one constant block, one memcpy ------------
#define WLM_STRIDE 68          // padded vocab row stride (16B-aligned rows)
#define OFF_WMLP   0           // [c][c2] 1024
#define OFF_BMLP   1024        // 32
#define OFF_BLM    1056        // 68 (65 + zero pad)
#define OFF_WLM    1124        // [c][v] 32*68 = 2176
#define PACK_N     3300
__device__   __align__(16) float g_pack[PACK_N];
__constant__ __align__(16) float c_all[PACK_N];

// smem copy of lm-head weights for vocab 0..31 (+ v64): [c][36] stride
#define WS_STRIDE 36           // 144 B rows -> 16B-aligned; col32 = v64
#define WS_N      (32 * WS_STRIDE)

// ---------------- packed f32x2 helpers (sm_103a) ----------------------------
__device__ __forceinline__ u64 fma2(u64 a, u64 b, u64 c) {
    u64 d; asm("fma.rn.f32x2 %0, %1, %2, %3;" : "=l"(d) : "l"(a), "l"(b), "l"(c)); return d;
}
__device__ __forceinline__ u64 add2(u64 a, u64 b) {
    u64 d; asm("add.rn.f32x2 %0, %1, %2;" : "=l"(d) : "l"(a), "l"(b)); return d;
}
__device__ __forceinline__ float hadd2(u64 a) {
    float lo, hi; asm("mov.b64 {%0,%1}, %2;" : "=f"(lo), "=f"(hi) : "l"(a)); return lo + hi;
}
__device__ __forceinline__ u64 pack2(float lo, float hi) {
    u64 r; asm("mov.b64 %0, {%1,%2};" : "=l"(r) : "f"(lo), "f"(hi)); return r;
}
__device__ __forceinline__ float lo2(u64 a) {
    float lo, hi; asm("mov.b64 {%0,%1}, %2;" : "=f"(lo), "=f"(hi) : "l"(a)); return lo;
}
__device__ __forceinline__ float hi2(u64 a) {
    float lo, hi; asm("mov.b64 {%0,%1}, %2;" : "=f"(lo), "=f"(hi) : "l"(a)); return hi;
}
__device__ __forceinline__ ulonglong2 ldc4(const float* p) {
    return *reinterpret_cast<const ulonglong2*>(p);
}

// Precompute Q/K/V tables AND pack weights for the single constant upload.
__global__ void k_tables(const float* __restrict__ tok_emb,
                         const float* __restrict__ pos_emb,
                         const float* __restrict__ Wq,
                         const float* __restrict__ Wk,
                         const float* __restrict__ Wv,
                         const float* __restrict__ Wmlp,
                         const float* __restrict__ bmlp,
                         const float* __restrict__ Wlm,
                         const float* __restrict__ blm) {
    int i = blockIdx.x * blockDim.x + threadIdx.x;
    if (i == 0) { g_loss = 0.0f; g_done = 0u; }
    if (i < 520 * 32) {
        int row = i >> 5, c = i & 31;
        int t = row / 65, tok = row % 65;
        int h = c >> 3, d = c & 7;
        float aq = 0.f, ak = 0.f, av = 0.f;
#pragma unroll
        for (int cc = 0; cc < 32; cc++) {
            float xv = tok_emb[tok * 32 + cc] + pos_emb[t * 32 + cc];
            int wi = h * 256 + cc * 8 + d;
            aq = fmaf(xv, Wq[wi], aq);
            ak = fmaf(xv, Wk[wi], ak);
            av = fmaf(xv, Wv[wi], av);
        }
        g_Qtab[i] = aq;
        g_Ktab[i] = ak * SQRT_C;
        g_Vtab[i] = av;
    } else {
        int i2 = i - 520 * 32;
        if (i2 < PACK_N) {
            float v;
            if (i2 < OFF_BMLP)      v = Wmlp[i2];
            else if (i2 < OFF_BLM)  v = bmlp[i2 - OFF_BMLP];
            else if (i2 < OFF_WLM) {
                int j = i2 - OFF_BLM;
                v = (j < 65) ? blm[j] : 0.0f;
            } else {
                int j  = i2 - OFF_WLM;
                int c  = j / WLM_STRIDE;
                int vv = j - c * WLM_STRIDE;
                v = (vv < 65) ? Wlm[c * 65 + vv] : 0.0f;
            }
            g_pack[i2] = v;
        }
    }
}

#define KV_LS_STRIDE 264   // floats per sequence: +8 banks per ls -> conflict-free

// Main fused kernel: one thread per (sequence, token). 128 threads = 16 seqs.
// PORT BALANCE: lm-head v0..31 + v64 weights via SMEM/LDS port; lm-head v32..63
// + MLP weights via CONSTANT port. The two streams run in parallel.
__global__ __launch_bounds__(128, 5)
void k_main(const int* __restrict__ idx, const int* __restrict__ tgt,
            float* __restrict__ out, int write_logits,
            int loss_idx, float inv_n, int nblocks) {
    // union: K at [ls*264+s*32], V at [4224+...]; later logits stage [128][65] dense
    __shared__ __align__(16) float s_un[8448];
    __shared__ __align__(16) float s_wlm2[WS_N];   // Wlm v0..31 (+v64 at col 32)
    __shared__ float               s_lred[4];

    const float* c_wmlp = c_all + OFF_WMLP;
    const float* c_bmlp = c_all + OFF_BMLP;
    const float* c_blm  = c_all + OFF_BLM;
    const float* c_wlm  = c_all + OFF_WLM;

    const int tid  = threadIdx.x;
    const int ls   = tid >> 3;                 // local sequence 0..15
    const int t    = tid & 7;                  // token position
    const int rowg = blockIdx.x * 128 + tid;   // global token row
    const int tok  = idx[rowg];
    const int tgtv = tgt[rowg];
    const int qrow = (t * 65 + tok) * 32;

    // stage lm-head smem weight tile: [c][36] = v0..31, v64, pad
    for (int i = tid; i < WS_N; i += 128) {
        int c = i / WS_STRIDE, col = i - c * WS_STRIDE;
        float v = 0.0f;
        if (col < 32)       v = g_pack[OFF_WLM + c * WLM_STRIDE + col];
        else if (col == 32) v = g_pack[OFF_WLM + c * WLM_STRIDE + 64];
        s_wlm2[i] = v;
    }

    // k, v rows into shared (own row; padded ls stride)
    {
        const float4* k4 = reinterpret_cast<const float4*>(g_Ktab + qrow);
        const float4* v4 = reinterpret_cast<const float4*>(g_Vtab + qrow);
        float4* skd = reinterpret_cast<float4*>(s_un + ls * KV_LS_STRIDE + t * 32);
        float4* svd = reinterpret_cast<float4*>(s_un + 4224 + ls * KV_LS_STRIDE + t * 32);
#pragma unroll
        for (int j = 0; j < 8; j++) { skd[j] = k4[j]; svd[j] = v4[j]; }
    }
    __syncthreads();

    // ----- attention in head-pairs (hp = heads {2hp, 2hp+1}) -----
    float ov[32];
#pragma unroll
    for (int hp = 0; hp < 2; hp++) {
        u64 q2[8];
        {
            const ulonglong2* q4 =
                reinterpret_cast<const ulonglong2*>(g_Qtab + qrow + hp * 16);
#pragma unroll
            for (int j = 0; j < 4; j++) {
                ulonglong2 a = q4[j];
                q2[2 * j] = a.x; q2[2 * j + 1] = a.y;
            }
        }
        float sc[2][8];
        const float* kb = s_un + ls * KV_LS_STRIDE + hp * 16;
#pragma unroll
        for (int s = 0; s < 8; s++) {
            const ulonglong2* kr = reinterpret_cast<const ulonglong2*>(kb + s * 32);
            ulonglong2 a = kr[0], b = kr[1], c = kr[2], d = kr[3];
            u64 e0 = 0ull, e1 = 0ull, f0 = 0ull, f1 = 0ull;
            e0 = fma2(q2[0], a.x, e0); e1 = fma2(q2[1], a.y, e1);
            e0 = fma2(q2[2], b.x, e0); e1 = fma2(q2[3], b.y, e1);
            f0 = fma2(q2[4], c.x, f0); f1 = fma2(q2[5], c.y, f1);
            f0 = fma2(q2[6], d.x, f0); f1 = fma2(q2[7], d.y, f1);
            float se = hadd2(add2(e0, e1));
            float sf = hadd2(add2(f0, f1));
            sc[0][s] = (s <= t) ? se : -1e30f;
            sc[1][s] = (s <= t) ? sf : -1e30f;
        }
        float rinv[2];
#pragma unroll
        for (int hh = 0; hh < 2; hh++) {
            float m = sc[hh][0];
#pragma unroll
            for (int s = 1; s < 8; s++) m = fmaxf(m, sc[hh][s]);
            float sum = 0.f;
#pragma unroll
            for (int s = 0; s < 8; s++) {
                float e = __expf(sc[hh][s] - m);   // masked lanes underflow to 0
                sc[hh][s] = e;
                sum += e;
            }
            rinv[hh] = __fdividef(1.0f, sum);
        }
        u64 oacc[8];
#pragma unroll
        for (int j = 0; j < 8; j++) oacc[j] = 0ull;
        const float* vb = s_un + 4224 + ls * KV_LS_STRIDE + hp * 16;
#pragma unroll
        for (int s = 0; s < 8; s++) {
            const ulonglong2* vr = reinterpret_cast<const ulonglong2*>(vb + s * 32);
            ulonglong2 a = vr[0], b = vr[1], c = vr[2], d = vr[3];
            float p0 = sc[0][s] * rinv[0];
            float p1 = sc[1][s] * rinv[1];
            u64 p02 = pack2(p0, p0), p12 = pack2(p1, p1);
            oacc[0] = fma2(p02, a.x, oacc[0]); oacc[1] = fma2(p02, a.y, oacc[1]);
            oacc[2] = fma2(p02, b.x, oacc[2]); oacc[3] = fma2(p02, b.y, oacc[3]);
            oacc[4] = fma2(p12, c.x, oacc[4]); oacc[5] = fma2(p12, c.y, oacc[5]);
            oacc[6] = fma2(p12, d.x, oacc[6]); oacc[7] = fma2(p12, d.y, oacc[7]);
        }
#pragma unroll
        for (int j = 0; j < 8; j++) {
            ov[hp * 16 + 2 * j]     = lo2(oacc[j]);
            ov[hp * 16 + 2 * j + 1] = hi2(oacc[j]);
        }
    }
    __syncthreads();   // done reading K/V -> union becomes logits stage

    // ----- MLP: y = relu(ov @ Wmlp + b); CONSTANT port -----
    u64 macc[16];
#pragma unroll
    for (int j = 0; j < 8; j++) {
        ulonglong2 b = ldc4(c_bmlp + 4 * j);
        macc[2 * j] = b.x; macc[2 * j + 1] = b.y;
    }
#pragma unroll
    for (int c = 0; c < 32; c++) {
        u64 xb = pack2(ov[c], ov[c]);
#pragma unroll
        for (int jj = 0; jj < 8; jj++) {
            ulonglong2 w = ldc4(c_wmlp + c * 32 + 4 * jj);
            macc[2 * jj]     = fma2(xb, w.x, macc[2 * jj]);
            macc[2 * jj + 1] = fma2(xb, w.y, macc[2 * jj + 1]);
        }
    }
    float y[32];
#pragma unroll
    for (int j = 0; j < 16; j++) {
        y[2 * j]     = fmaxf(lo2(macc[j]), 0.f);
        y[2 * j + 1] = fmaxf(hi2(macc[j]), 0.f);
    }

    // ----- lm-head: chunks 0-1 weights via SMEM, chunks 2-3 via CONSTANT -----
    float* stagerow = s_un + tid * 65;          // dense stage = output layout
    float m = -1e30f, sum = 0.f;

#define LM_CHUNK(WPTR_EXPR)                                                   \
    {                                                                         \
        u64 acc[8];                                                           \
        _Pragma("unroll")                                                     \
        for (int p = 0; p < 4; p++) {                                         \
            ulonglong2 b = ldc4(c_blm + vb + 4 * p);                          \
            acc[2 * p] = b.x; acc[2 * p + 1] = b.y;                           \
        }                                                                     \
        _Pragma("unroll")                                                     \
        for (int c = 0; c < 32; c++) {                                        \
            u64 yb = pack2(y[c], y[c]);                                       \
            const float* wr = (WPTR_EXPR);                                    \
            _Pragma("unroll")                                                 \
            for (int q = 0; q < 4; q++) {                                     \
                ulonglong2 w = *reinterpret_cast<const ulonglong2*>(wr + 4 * q); \
                acc[2 * q]     = fma2(yb, w.x, acc[2 * q]);                   \
                acc[2 * q + 1] = fma2(yb, w.y, acc[2 * q + 1]);               \
            }                                                                 \
        }                                                                     \
        float cm = -1e30f;                                                    \
        float l[16];                                                          \
        _Pragma("unroll")                                                     \
        for (int p = 0; p < 8; p++) {                                         \
            l[2 * p] = lo2(acc[p]); l[2 * p + 1] = hi2(acc[p]);               \
            stagerow[vb + 2 * p]     = l[2 * p];                              \
            stagerow[vb + 2 * p + 1] = l[2 * p + 1];                          \
            cm = fmaxf(cm, fmaxf(l[2 * p], l[2 * p + 1]));                    \
        }                                                                     \
        float mn = fmaxf(m, cm);                                              \
        float s2 = sum * __expf(m - mn);                                      \
        _Pragma("unroll")                                                     \
        for (int p = 0; p < 16; p++) s2 += __expf(l[p] - mn);                 \
        m = mn; sum = s2;                                                     \
    }

#pragma unroll
    for (int chunk = 0; chunk < 2; chunk++) {      // v0..31 from SMEM
        const int vb = chunk * 16;
        LM_CHUNK(s_wlm2 + c * WS_STRIDE + vb)
    }
#pragma unroll
    for (int chunk = 2; chunk < 4; chunk++) {      // v32..63 from CONSTANT
        const int vb = chunk * 16;
        LM_CHUNK(c_wlm + c * WLM_STRIDE + vb)
    }
    {   // epilogue: v = 64 from SMEM col 32 (pair partner is zero pad)
        u64 acc = *reinterpret_cast<const u64*>(c_blm + 64);
#pragma unroll
        for (int c = 0; c < 32; c++) {
            u64 yb = pack2(y[c], y[c]);
            u64 w = *reinterpret_cast<const u64*>(s_wlm2 + c * WS_STRIDE + 32);
            acc = fma2(yb, w, acc);
        }
        float l64 = lo2(acc);
        stagerow[64] = l64;
        float mn = fmaxf(m, l64);
        sum = sum * __expf(m - mn) + __expf(l64 - mn);
        m = mn;
    }
    float ltgt  = stagerow[tgtv];              // own row, no sync needed
    float lossi = (m + __logf(sum)) - ltgt;

    // warp then block reduce, one atomic per block; last block writes mean
#pragma unroll
    for (int off = 16; off > 0; off >>= 1)
        lossi += __shfl_down_sync(0xffffffffu, lossi, off);
    if ((tid & 31) == 0) s_lred[tid >> 5] = lossi;
    __syncthreads();    // also guarantees stage[] fully written for the bulk store
    if (tid == 0) {
        atomicAdd(&g_loss, s_lred[0] + s_lred[1] + s_lred[2] + s_lred[3]);
        __threadfence();
        unsigned prev = atomicAdd(&g_done, 1u);
        if ((int)prev == nblocks - 1 && loss_idx >= 0)
            out[loss_idx] = g_loss * inv_n;
    }

    // ----- single TMA bulk store: SMEM stage -> GMEM logits (33280 B) -----
    if (write_logits && tid == 0) {
        u32 saddr;
        asm("{ .reg .u64 tmp; cvta.to.shared.u64 tmp, %1; cvt.u32.u64 %0, tmp; }"
            : "=r"(saddr) : "l"(s_un));
        const float* gdst = out + (size_t)blockIdx.x * 8320;
        asm volatile("fence.proxy.async.shared::cta;" ::: "memory");
        asm volatile("cp.async.bulk.global.shared::cta.bulk_group [%0], [%1], %2;"
                     :: "l"(gdst), "r"(saddr), "r"(33280) : "memory");
        asm volatile("cp.async.bulk.commit_group;" ::: "memory");
        asm volatile("cp.async.bulk.wait_group.read 0;" ::: "memory");
    }
}

extern "C" void kernel_launch(void* const* d_in, const int* in_sizes, int n_in,
                              void* d_out, int out_size) {
    const int*   idx     = (const int*)d_in[0];
    const int*   targets = (const int*)d_in[1];
    const float* tok_emb = (const float*)d_in[2];
    const float* pos_emb = (const float*)d_in[3];
    const float* Wq      = (const float*)d_in[4];
    const float* Wk      = (const float*)d_in[5];
    const float* Wv      = (const float*)d_in[6];
    const float* Wmlp    = (const float*)d_in[7];
    const float* bmlp    = (const float*)d_in[8];
    const float* Wlm     = (const float*)d_in[9];
    const float* blm     = (const float*)d_in[10];
    float* out = (float*)d_out;

    const long nrows = in_sizes[0];           // B*T = 524288
    const long total = nrows * VOCAB;
    int write_logits = ((long)out_size >= total) ? 1 : 0;
    int loss_idx = -1;
    if ((long)out_size == total + 1) loss_idx = (int)total;
    else if (out_size == 1)          { loss_idx = 0; write_logits = 0; }

    int work = 520 * 32 + PACK_N;
    k_tables<<<(work + 255) / 256, 256>>>(tok_emb, pos_emb, Wq, Wk, Wv,
                                          Wmlp, bmlp, Wlm, blm);
    {
        void* src = nullptr;
        cudaGetSymbolAddress(&src, g_pack);
        cudaMemcpyToSymbolAsync(c_all, src, PACK_N * sizeof(float), 0,
                                cudaMemcpyDeviceToDevice);
    }

    int nblocks = (int)(nrows / 128);
    k_main<<<nblocks, 128>>>(idx, targets, out, write_logits, loss_idx,
                             1.0f / (float)nrows, nblocks);
}